// round 14
// baseline (speedup 1.0000x reference)
#include <cuda_runtime.h>
#include <cuda_bf16.h>
#include <cstdint>

// x:   [B=64, C=12, 224, 224] fp32
// w:   [C=12, E=768] fp32
// out: [B=64, P=196, E=768] fp32
//
// CTA = 2x2 patch block x 2 batches, software-pipelined:
//   fire cp.async for batch1 (smem, zero regs) -> LDG+reduce batch0 ->
//   phase2(batch0) overlaps batch1's DRAM latency -> read smem, reduce ->
//   phase2(batch1). Only the final tail is read-idle.

#define IMG    224
#define NP     14
#define C_IN   12
#define EMBED  768
#define NTH    384
#define BSTRIDE ((size_t)C_IN * IMG * IMG)   // floats between batches

struct __align__(16) SmemT {
    float4 buf[C_IN * 8 * 32];   // 48 KB: batch-1 tile [channel][k][lane]
    float  pooled0[C_IN][4];
    float  pooled1[C_IN][4];
};

__device__ __forceinline__ void cp16(uint32_t dst, const float* src) {
    asm volatile("cp.async.cg.shared.global [%0], [%1], 16;"
                 :: "r"(dst), "l"(src) : "memory");
}

__global__ __launch_bounds__(NTH, 3) void patch_pipe_kernel(
    const float* __restrict__ x,
    const float* __restrict__ w,
    float* __restrict__ out)
{
    __shared__ SmemT s;

    const int pp  = blockIdx.x;        // patch-col pair 0..6
    const int pr  = blockIdx.y;        // patch-row pair 0..6
    const int bz  = blockIdx.z;        // batch pair 0..31
    const int t   = threadIdx.x;
    const int warp = t >> 5;           // channel 0..11
    const int lane = t & 31;
    const int q8  = lane & 7;          // float4 col within the 32-float row
    const int rh  = lane >> 3;         // row phase 0..3

    const float* base0 = x
        + (((size_t)((2 * bz) * C_IN + warp)) * IMG + (size_t)pr * 32 + rh) * IMG
        + (size_t)pp * 32 + q8 * 4;
    const float* base1 = base0 + BSTRIDE;

    // ---- 1) fire batch-1 loads into smem (no register staging) ----
    {
        const uint32_t dst0 = (uint32_t)__cvta_generic_to_shared(
            &s.buf[(warp * 8) * 32 + lane]);
        #pragma unroll
        for (int k = 0; k < 8; ++k)
            cp16(dst0 + k * 32 * 16, base1 + (size_t)(4 * k) * IMG);
        asm volatile("cp.async.commit_group;" ::: "memory");
    }

    // ---- 2) batch 0: 8 staged LDG.128 + dual shuffle-reduce (R7) ----
    {
        float4 u0 = *reinterpret_cast<const float4*>(base0 + (size_t)(4 * 0) * IMG);
        float4 u1 = *reinterpret_cast<const float4*>(base0 + (size_t)(4 * 1) * IMG);
        float4 u2 = *reinterpret_cast<const float4*>(base0 + (size_t)(4 * 2) * IMG);
        float4 u3 = *reinterpret_cast<const float4*>(base0 + (size_t)(4 * 3) * IMG);
        float4 d0 = *reinterpret_cast<const float4*>(base0 + (size_t)(4 * 4) * IMG);
        float4 d1 = *reinterpret_cast<const float4*>(base0 + (size_t)(4 * 5) * IMG);
        float4 d2 = *reinterpret_cast<const float4*>(base0 + (size_t)(4 * 6) * IMG);
        float4 d3 = *reinterpret_cast<const float4*>(base0 + (size_t)(4 * 7) * IMG);

        float st = (((u0.x + u0.y) + (u0.z + u0.w)) + ((u1.x + u1.y) + (u1.z + u1.w)))
                 + (((u2.x + u2.y) + (u2.z + u2.w)) + ((u3.x + u3.y) + (u3.z + u3.w)));
        float sb = (((d0.x + d0.y) + (d0.z + d0.w)) + ((d1.x + d1.y) + (d1.z + d1.w)))
                 + (((d2.x + d2.y) + (d2.z + d2.w)) + ((d3.x + d3.y) + (d3.z + d3.w)));

        st += __shfl_xor_sync(0xffffffffu, st, 1);
        sb += __shfl_xor_sync(0xffffffffu, sb, 1);
        st += __shfl_xor_sync(0xffffffffu, st, 2);
        sb += __shfl_xor_sync(0xffffffffu, sb, 2);
        st += __shfl_xor_sync(0xffffffffu, st, 8);
        sb += __shfl_xor_sync(0xffffffffu, sb, 8);
        st += __shfl_xor_sync(0xffffffffu, st, 16);
        sb += __shfl_xor_sync(0xffffffffu, sb, 16);

        if ((lane & 27) == 0) {
            const int pc = (lane >> 2) & 1;
            s.pooled0[warp][pc]     = st;
            s.pooled0[warp][2 + pc] = sb;
        }
    }
    __syncthreads();

    const int e4 = t % 192;
    const int lr = t / 192;
    const int pi = pr * 2 + lr;
    const int pj = pp * 2;

    // ---- 3) phase2(batch 0): overlaps batch-1 cp.async latency ----
    {
        float4 acc0 = make_float4(0.f, 0.f, 0.f, 0.f);
        float4 acc1 = make_float4(0.f, 0.f, 0.f, 0.f);
        #pragma unroll
        for (int c = 0; c < C_IN; ++c) {
            const float4 wv = *reinterpret_cast<const float4*>(&w[c * EMBED + e4 * 4]);
            const float p0 = s.pooled0[c][lr * 2 + 0];
            const float p1 = s.pooled0[c][lr * 2 + 1];
            acc0.x = fmaf(p0, wv.x, acc0.x);  acc1.x = fmaf(p1, wv.x, acc1.x);
            acc0.y = fmaf(p0, wv.y, acc0.y);  acc1.y = fmaf(p1, wv.y, acc1.y);
            acc0.z = fmaf(p0, wv.z, acc0.z);  acc1.z = fmaf(p1, wv.z, acc1.z);
            acc0.w = fmaf(p0, wv.w, acc0.w);  acc1.w = fmaf(p1, wv.w, acc1.w);
        }
        float* o = out + ((size_t)(2 * bz) * (NP * NP) + (size_t)pi * NP + pj) * EMBED
                       + e4 * 4;
        *reinterpret_cast<float4*>(o)         = acc0;
        *reinterpret_cast<float4*>(o + EMBED) = acc1;
    }

    // ---- 4) batch 1: drain cp.async, read own slots, reduce ----
    asm volatile("cp.async.wait_group 0;" ::: "memory");
    {
        const float4 u0 = s.buf[(warp * 8 + 0) * 32 + lane];
        const float4 u1 = s.buf[(warp * 8 + 1) * 32 + lane];
        const float4 u2 = s.buf[(warp * 8 + 2) * 32 + lane];
        const float4 u3 = s.buf[(warp * 8 + 3) * 32 + lane];
        const float4 d0 = s.buf[(warp * 8 + 4) * 32 + lane];
        const float4 d1 = s.buf[(warp * 8 + 5) * 32 + lane];
        const float4 d2 = s.buf[(warp * 8 + 6) * 32 + lane];
        const float4 d3 = s.buf[(warp * 8 + 7) * 32 + lane];

        float st = (((u0.x + u0.y) + (u0.z + u0.w)) + ((u1.x + u1.y) + (u1.z + u1.w)))
                 + (((u2.x + u2.y) + (u2.z + u2.w)) + ((u3.x + u3.y) + (u3.z + u3.w)));
        float sb = (((d0.x + d0.y) + (d0.z + d0.w)) + ((d1.x + d1.y) + (d1.z + d1.w)))
                 + (((d2.x + d2.y) + (d2.z + d2.w)) + ((d3.x + d3.y) + (d3.z + d3.w)));

        st += __shfl_xor_sync(0xffffffffu, st, 1);
        sb += __shfl_xor_sync(0xffffffffu, sb, 1);
        st += __shfl_xor_sync(0xffffffffu, st, 2);
        sb += __shfl_xor_sync(0xffffffffu, sb, 2);
        st += __shfl_xor_sync(0xffffffffu, st, 8);
        sb += __shfl_xor_sync(0xffffffffu, sb, 8);
        st += __shfl_xor_sync(0xffffffffu, st, 16);
        sb += __shfl_xor_sync(0xffffffffu, sb, 16);

        if ((lane & 27) == 0) {
            const int pc = (lane >> 2) & 1;
            s.pooled1[warp][pc]     = st;
            s.pooled1[warp][2 + pc] = sb;
        }
    }
    __syncthreads();

    // ---- 5) phase2(batch 1) ----
    {
        float4 acc0 = make_float4(0.f, 0.f, 0.f, 0.f);
        float4 acc1 = make_float4(0.f, 0.f, 0.f, 0.f);
        #pragma unroll
        for (int c = 0; c < C_IN; ++c) {
            const float4 wv = *reinterpret_cast<const float4*>(&w[c * EMBED + e4 * 4]);
            const float p0 = s.pooled1[c][lr * 2 + 0];
            const float p1 = s.pooled1[c][lr * 2 + 1];
            acc0.x = fmaf(p0, wv.x, acc0.x);  acc1.x = fmaf(p1, wv.x, acc1.x);
            acc0.y = fmaf(p0, wv.y, acc0.y);  acc1.y = fmaf(p1, wv.y, acc1.y);
            acc0.z = fmaf(p0, wv.z, acc0.z);  acc1.z = fmaf(p1, wv.z, acc1.z);
            acc0.w = fmaf(p0, wv.w, acc0.w);  acc1.w = fmaf(p1, wv.w, acc1.w);
        }
        float* o = out + ((size_t)(2 * bz + 1) * (NP * NP) + (size_t)pi * NP + pj) * EMBED
                       + e4 * 4;
        *reinterpret_cast<float4*>(o)         = acc0;
        *reinterpret_cast<float4*>(o + EMBED) = acc1;
    }
}

extern "C" void kernel_launch(void* const* d_in, const int* in_sizes, int n_in,
                              void* d_out, int out_size)
{
    const float* x = (const float*)d_in[0];
    const float* w = (const float*)d_in[1];
    float* out = (float*)d_out;

    dim3 grid(7, 7, 32);   // 1568 CTAs
    patch_pipe_kernel<<<grid, NTH>>>(x, w, out);
}

// round 15
// speedup vs baseline: 1.2410x; 1.2410x over previous
#include <cuda_runtime.h>
#include <cuda_bf16.h>
#include <cstdint>

// x:   [B=64, C=12, 224, 224] fp32
// w:   [C=12, E=768] fp32
// out: [B=64, P=196, E=768] fp32
//
// CTA = one horizontal patch pair (16 rows x 32 cols x 12 channels = 24 KB),
// 192 threads / 6 warps. Each warp pools TWO channels; each thread issues the
// proven 8 independent staged LDG.128 (4 rows per channel, full 128B lines).
// 6 CTAs/SM (same 36 warps as the 384-thread variant, but twice as many
// independent CTAs interleaving load bursts with reduce/epilogue tails).

#define IMG    224
#define NP     14
#define C_IN   12
#define EMBED  768
#define NTH    192
#define CH_STRIDE ((size_t)IMG * IMG)   // floats between channels

__global__ __launch_bounds__(NTH, 6) void patch_pair6_kernel(
    const float* __restrict__ x,
    const float* __restrict__ w,
    float* __restrict__ out)
{
    const int pp  = blockIdx.x;        // patch-col pair 0..6
    const int pi  = blockIdx.y;        // patch row 0..13
    const int b   = blockIdx.z;        // 0..63
    const int t   = threadIdx.x;
    const int warp = t >> 5;           // 0..5 -> channels 2w, 2w+1
    const int lane = t & 31;
    const int q8  = lane & 7;          // float4 col within the 32-float row
    const int rh  = lane >> 3;         // row phase 0..3

    __shared__ float pooled[C_IN][2];  // [channel][patch col]

    // ---- Phase 1: warp pools 16x32 of channels 2w and 2w+1 ----
    const float* base0 = x
        + (((size_t)(b * C_IN + 2 * warp)) * IMG + (size_t)pi * 16 + rh) * IMG
        + (size_t)pp * 32 + q8 * 4;
    const float* base1 = base0 + CH_STRIDE;

    // 8 independent LDG.128 (rows rh+4k, k=0..3, for both channels)
    float4 a0 = *reinterpret_cast<const float4*>(base0 + (size_t)(4 * 0) * IMG);
    float4 a1 = *reinterpret_cast<const float4*>(base0 + (size_t)(4 * 1) * IMG);
    float4 a2 = *reinterpret_cast<const float4*>(base0 + (size_t)(4 * 2) * IMG);
    float4 a3 = *reinterpret_cast<const float4*>(base0 + (size_t)(4 * 3) * IMG);
    float4 b0 = *reinterpret_cast<const float4*>(base1 + (size_t)(4 * 0) * IMG);
    float4 b1 = *reinterpret_cast<const float4*>(base1 + (size_t)(4 * 1) * IMG);
    float4 b2 = *reinterpret_cast<const float4*>(base1 + (size_t)(4 * 2) * IMG);
    float4 b3 = *reinterpret_cast<const float4*>(base1 + (size_t)(4 * 3) * IMG);

    float s0 = (((a0.x + a0.y) + (a0.z + a0.w)) + ((a1.x + a1.y) + (a1.z + a1.w)))
             + (((a2.x + a2.y) + (a2.z + a2.w)) + ((a3.x + a3.y) + (a3.z + a3.w)));
    float s1 = (((b0.x + b0.y) + (b0.z + b0.w)) + ((b1.x + b1.y) + (b1.z + b1.w)))
             + (((b2.x + b2.y) + (b2.z + b2.w)) + ((b3.x + b3.y) + (b3.z + b3.w)));

    // Fold lane bits 0,1 (float4 cols within a patch) and 3,4 (row phases);
    // bit 2 (q8>>2) = patch column survives.
    s0 += __shfl_xor_sync(0xffffffffu, s0, 1);
    s1 += __shfl_xor_sync(0xffffffffu, s1, 1);
    s0 += __shfl_xor_sync(0xffffffffu, s0, 2);
    s1 += __shfl_xor_sync(0xffffffffu, s1, 2);
    s0 += __shfl_xor_sync(0xffffffffu, s0, 8);
    s1 += __shfl_xor_sync(0xffffffffu, s1, 8);
    s0 += __shfl_xor_sync(0xffffffffu, s0, 16);
    s1 += __shfl_xor_sync(0xffffffffu, s1, 16);

    if ((lane & 27) == 0) {            // lanes 0 and 4
        const int pc = (lane >> 2) & 1;
        pooled[2 * warp + 0][pc] = s0;
        pooled[2 * warp + 1][pc] = s1;
    }
    __syncthreads();

    // ---- Phase 2: one w column read serves both patch outputs ----
    float4 acc0 = make_float4(0.f, 0.f, 0.f, 0.f);  // patch col 0
    float4 acc1 = make_float4(0.f, 0.f, 0.f, 0.f);  // patch col 1
    #pragma unroll
    for (int c = 0; c < C_IN; ++c) {
        const float4 wv = *reinterpret_cast<const float4*>(&w[c * EMBED + t * 4]);
        const float p0 = pooled[c][0];
        const float p1 = pooled[c][1];
        acc0.x = fmaf(p0, wv.x, acc0.x);  acc1.x = fmaf(p1, wv.x, acc1.x);
        acc0.y = fmaf(p0, wv.y, acc0.y);  acc1.y = fmaf(p1, wv.y, acc1.y);
        acc0.z = fmaf(p0, wv.z, acc0.z);  acc1.z = fmaf(p1, wv.z, acc1.z);
        acc0.w = fmaf(p0, wv.w, acc0.w);  acc1.w = fmaf(p1, wv.w, acc1.w);
    }

    float* o = out + ((size_t)b * (NP * NP) + (size_t)pi * NP + pp * 2) * EMBED + t * 4;
    *reinterpret_cast<float4*>(o)         = acc0;   // patch (pi, 2pp)
    *reinterpret_cast<float4*>(o + EMBED) = acc1;   // patch (pi, 2pp+1)
}

extern "C" void kernel_launch(void* const* d_in, const int* in_sizes, int n_in,
                              void* d_out, int out_size)
{
    const float* x = (const float*)d_in[0];
    const float* w = (const float*)d_in[1];
    float* out = (float*)d_out;

    dim3 grid(7, NP, 64);   // 6272 CTAs
    patch_pair6_kernel<<<grid, NTH>>>(x, w, out);
}